// round 16
// baseline (speedup 1.0000x reference)
#include <cuda_runtime.h>
#include <cstdint>

// Shapes (fixed by the problem)
#define BATCH   2
#define SEQ     4096
#define HEADS   16
#define DHEAD   64      // p
#define DSTATE  128     // n
#define LBLK    64      // block_len l

// ============================================================================
// FINAL KERNEL (frozen at R12 structure; best measured ncu dur = 6.18-6.24us)
//
// Math: reference's decay_chunk row z=C (upper-triangular mask j>=i) keeps
// ONLY column j=C -> output depends on the LAST 64 timesteps alone:
//   out[b,h,p,n] = sum_l exp(2*S - cs[l]) * X[b,T-64+l,h,p] * B[b,T-64+l,h,n]
// with cs = inclusive cumsum of A over the last 64 steps, S = cs[63].
// w folded into B:  out = sum_l X_l (outer) (w_l * B_l).
//
// Structure:
//  - 128 CTAs (one wave), 256 threads, 2p x 4n register microtile.
//  - B and X staged via cp.async in SEPARATE commit groups; the w-premultiply
//    of Bs runs under X's in-flight DRAM latency (wait_group 1 ... wait_group 0).
//  - A scanned by warp 0 (shuffle pair-scan) concurrently with cp.async flight.
//  - Inner product uses packed fma.rn.f32x2 (Blackwell FFMA2, PTX-only) to
//    halve fma-pipe issue slots.
// ============================================================================

__device__ __forceinline__ void cp_async16(uint32_t saddr, const void* gptr) {
    asm volatile("cp.async.cg.shared.global [%0], [%1], 16;"
                 :: "r"(saddr), "l"(gptr));
}

__global__ __launch_bounds__(256)
void chunk_state_last_kernel(const float* __restrict__ X,
                             const float* __restrict__ A,
                             const float* __restrict__ B,
                             float* __restrict__ out)
{
    const int bh = blockIdx.x;          // 0..31
    const int b  = bh >> 4;
    const int h  = bh & 15;
    const int n0 = blockIdx.y * 32;     // n-tile origin (4 tiles of 32)
    const int tid = threadIdx.x;        // 256 threads
    const int t0 = SEQ - LBLK;

    __shared__ __align__(16) float  Xs[LBLK][DHEAD];  // 16 KB [l][p]
    __shared__ __align__(16) float4 Bs[LBLK][8];      //  8 KB [l][n/4]
    __shared__ __align__(16) float  w[LBLK];

    // ---- 1a) stage B tile in its own group (completes first) ----
    const float* Bbase = B + (((size_t)b * SEQ + t0) * HEADS + h) * DSTATE + n0;
    const uint32_t bs_s = (uint32_t)__cvta_generic_to_shared(&Bs[0][0]);
    #pragma unroll
    for (int k = 0; k < 2; k++) {
        int i = tid + k * 256;          // 0..511 float4 slots
        int l = i >> 3, c = i & 7;
        cp_async16(bs_s + i * 16, Bbase + (size_t)l * HEADS * DSTATE + c * 4);
    }
    asm volatile("cp.async.commit_group;");   // group: B

    // ---- 1b) stage X tile (second group) ----
    const float* Xbase = X + (((size_t)b * SEQ + t0) * HEADS + h) * DHEAD;
    const uint32_t xs_s = (uint32_t)__cvta_generic_to_shared(&Xs[0][0]);
    #pragma unroll
    for (int k = 0; k < 4; k++) {
        int i = tid + k * 256;          // 0..1023 float4 slots
        int l = i >> 4, c = i & 15;
        cp_async16(xs_s + i * 16, Xbase + (size_t)l * HEADS * DHEAD + c * 4);
    }
    asm volatile("cp.async.commit_group;");   // group: X

    // ---- 2) warp 0 only: A scan (2 values/lane, pair-scan) + weights ----
    if (tid < 32) {
        const int lane = tid;
        const float* Abase = A + ((size_t)b * SEQ + t0) * HEADS + h;
        float a0 = Abase[(size_t)(2 * lane)     * HEADS];
        float a1 = Abase[(size_t)(2 * lane + 1) * HEADS];
        float v = a0 + a1;              // pair sum
        #pragma unroll
        for (int off = 1; off < 32; off <<= 1) {
            float up = __shfl_up_sync(0xFFFFFFFFu, v, off);
            if (lane >= off) v += up;
        }
        float S   = __shfl_sync(0xFFFFFFFFu, v, 31);  // total sum cs[63]
        float cs1 = v;                  // inclusive cumsum through 2*lane+1
        float cs0 = v - a1;             // inclusive cumsum through 2*lane
        w[2 * lane]     = __expf(2.f * S - cs0);
        w[2 * lane + 1] = __expf(2.f * S - cs1);
    }

    // ---- 3) premultiply w into Bs while X is still in flight ----
    asm volatile("cp.async.wait_group 1;");   // B group landed (X may be pending)
    __syncthreads();                          // w + Bs visible to all
    #pragma unroll
    for (int k = 0; k < 2; k++) {
        int i = tid + k * 256;
        float4* p4 = (float4*)&Bs[0][0] + i;
        float4 v = *p4;
        float wl = w[i >> 3];
        v.x *= wl; v.y *= wl; v.z *= wl; v.w *= wl;
        *p4 = v;
    }
    asm volatile("cp.async.wait_group 0;");   // X landed
    __syncthreads();                          // Bs(premul) + Xs ready

    // ---- 4) rank-64 outer product; 2p x 4n per thread, packed f32x2 ----
    const int tn = tid & 7;             // n = n0 + tn*4 + j
    const int tp = tid >> 3;            // p = tp*2 + {0,1}

    unsigned long long a00 = 0ULL, a01 = 0ULL;   // p0: (j0,j1), (j2,j3)
    unsigned long long a10 = 0ULL, a11 = 0ULL;   // p1

    #pragma unroll 8
    for (int l = 0; l < LBLK; l++) {
        const float2 xv = *(const float2*)&Xs[l][tp * 2];
        const ulonglong2 bq = *(const ulonglong2*)&Bs[l][tn];  // w pre-applied
        unsigned long long xd0, xd1;
        asm("mov.b64 %0, {%1, %1};" : "=l"(xd0) : "r"(__float_as_uint(xv.x)));
        asm("mov.b64 %0, {%1, %1};" : "=l"(xd1) : "r"(__float_as_uint(xv.y)));
        asm("fma.rn.f32x2 %0, %1, %2, %0;" : "+l"(a00) : "l"(xd0), "l"(bq.x));
        asm("fma.rn.f32x2 %0, %1, %2, %0;" : "+l"(a01) : "l"(xd0), "l"(bq.y));
        asm("fma.rn.f32x2 %0, %1, %2, %0;" : "+l"(a10) : "l"(xd1), "l"(bq.x));
        asm("fma.rn.f32x2 %0, %1, %2, %0;" : "+l"(a11) : "l"(xd1), "l"(bq.y));
    }

    // packed pairs are little-endian (low float first) == float4 layout
    float* obase = out + ((size_t)(b * HEADS + h)) * DHEAD * DSTATE;
    *(ulonglong2*)(obase + (size_t)(tp * 2)     * DSTATE + n0 + tn * 4) =
        make_ulonglong2(a00, a01);
    *(ulonglong2*)(obase + (size_t)(tp * 2 + 1) * DSTATE + n0 + tn * 4) =
        make_ulonglong2(a10, a11);
}

extern "C" void kernel_launch(void* const* d_in, const int* in_sizes, int n_in,
                              void* d_out, int out_size)
{
    const float* X = (const float*)d_in[0];   // (2,4096,16,64)  f32
    const float* A = (const float*)d_in[1];   // (2,4096,16)     f32
    const float* B = (const float*)d_in[2];   // (2,4096,16,128) f32
    float* out = (float*)d_out;               // (2,16,64,128)   f32

    dim3 grid(BATCH * HEADS, DSTATE / 32);    // 32 x 4 = 128 CTAs
    chunk_state_last_kernel<<<grid, 256>>>(X, A, B, out);
}

// round 17
// speedup vs baseline: 1.1333x; 1.1333x over previous
#include <cuda_runtime.h>
#include <cstdint>

// Shapes (fixed by the problem)
#define BATCH   2
#define SEQ     4096
#define HEADS   16
#define DHEAD   64      // p
#define DSTATE  128     // n
#define LBLK    64      // block_len l

// ============================================================================
// FINAL KERNEL (frozen; best measured ncu dur 6.18us, noise band +/-0.5us)
//
// Math: reference's decay_chunk row z=C (upper-triangular mask j>=i) keeps
// ONLY column j=C -> output depends on the LAST 64 timesteps alone:
//   out[b,h,p,n] = sum_l exp(2*S - cs[l]) * X[b,T-64+l,h,p] * B[b,T-64+l,h,n]
// with cs = inclusive cumsum of A over the last 64 steps, S = cs[63].
// w folded into B:  out = sum_l X_l (outer) (w_l * B_l).
// This removes 99.4% of the reference's FLOPs/bytes (reads 1.5MB, not 25MB).
//
// Structure:
//  - 128 CTAs (one wave), 256 threads, 2p x 4n register microtile.
//  - B and X staged via cp.async in SEPARATE commit groups; the w-premultiply
//    of Bs runs under X's in-flight DRAM latency (wait_group 1 ... wait_group 0).
//  - A scanned by warp 0 (shuffle pair-scan) concurrently with cp.async flight.
//  - Inner product uses packed fma.rn.f32x2 (Blackwell FFMA2, PTX-only) to
//    halve fma-pipe issue slots.
// Session evidence: loop-length split (R8), FFMA halving (R9), barrier
// elision (R14) all moved <5% or regressed -> kernel is launch/ramp/latency
// overhead-bound; DRAM 3%, fma 7%, tensor 0%. Frozen.
// ============================================================================

__device__ __forceinline__ void cp_async16(uint32_t saddr, const void* gptr) {
    asm volatile("cp.async.cg.shared.global [%0], [%1], 16;"
                 :: "r"(saddr), "l"(gptr));
}

__global__ __launch_bounds__(256)
void chunk_state_last_kernel(const float* __restrict__ X,
                             const float* __restrict__ A,
                             const float* __restrict__ B,
                             float* __restrict__ out)
{
    const int bh = blockIdx.x;          // 0..31
    const int b  = bh >> 4;
    const int h  = bh & 15;
    const int n0 = blockIdx.y * 32;     // n-tile origin (4 tiles of 32)
    const int tid = threadIdx.x;        // 256 threads
    const int t0 = SEQ - LBLK;

    __shared__ __align__(16) float  Xs[LBLK][DHEAD];  // 16 KB [l][p]
    __shared__ __align__(16) float4 Bs[LBLK][8];      //  8 KB [l][n/4]
    __shared__ __align__(16) float  w[LBLK];

    // ---- 1a) stage B tile in its own group (completes first) ----
    const float* Bbase = B + (((size_t)b * SEQ + t0) * HEADS + h) * DSTATE + n0;
    const uint32_t bs_s = (uint32_t)__cvta_generic_to_shared(&Bs[0][0]);
    #pragma unroll
    for (int k = 0; k < 2; k++) {
        int i = tid + k * 256;          // 0..511 float4 slots
        int l = i >> 3, c = i & 7;
        cp_async16(bs_s + i * 16, Bbase + (size_t)l * HEADS * DSTATE + c * 4);
    }
    asm volatile("cp.async.commit_group;");   // group: B

    // ---- 1b) stage X tile (second group) ----
    const float* Xbase = X + (((size_t)b * SEQ + t0) * HEADS + h) * DHEAD;
    const uint32_t xs_s = (uint32_t)__cvta_generic_to_shared(&Xs[0][0]);
    #pragma unroll
    for (int k = 0; k < 4; k++) {
        int i = tid + k * 256;          // 0..1023 float4 slots
        int l = i >> 4, c = i & 15;
        cp_async16(xs_s + i * 16, Xbase + (size_t)l * HEADS * DHEAD + c * 4);
    }
    asm volatile("cp.async.commit_group;");   // group: X

    // ---- 2) warp 0 only: A scan (2 values/lane, pair-scan) + weights ----
    if (tid < 32) {
        const int lane = tid;
        const float* Abase = A + ((size_t)b * SEQ + t0) * HEADS + h;
        float a0 = Abase[(size_t)(2 * lane)     * HEADS];
        float a1 = Abase[(size_t)(2 * lane + 1) * HEADS];
        float v = a0 + a1;              // pair sum
        #pragma unroll
        for (int off = 1; off < 32; off <<= 1) {
            float up = __shfl_up_sync(0xFFFFFFFFu, v, off);
            if (lane >= off) v += up;
        }
        float S   = __shfl_sync(0xFFFFFFFFu, v, 31);  // total sum cs[63]
        float cs1 = v;                  // inclusive cumsum through 2*lane+1
        float cs0 = v - a1;             // inclusive cumsum through 2*lane
        w[2 * lane]     = __expf(2.f * S - cs0);
        w[2 * lane + 1] = __expf(2.f * S - cs1);
    }

    // ---- 3) premultiply w into Bs while X is still in flight ----
    asm volatile("cp.async.wait_group 1;");   // B group landed (X may be pending)
    __syncthreads();                          // w + Bs visible to all
    #pragma unroll
    for (int k = 0; k < 2; k++) {
        int i = tid + k * 256;
        float4* p4 = (float4*)&Bs[0][0] + i;
        float4 v = *p4;
        float wl = w[i >> 3];
        v.x *= wl; v.y *= wl; v.z *= wl; v.w *= wl;
        *p4 = v;
    }
    asm volatile("cp.async.wait_group 0;");   // X landed
    __syncthreads();                          // Bs(premul) + Xs ready

    // ---- 4) rank-64 outer product; 2p x 4n per thread, packed f32x2 ----
    const int tn = tid & 7;             // n = n0 + tn*4 + j
    const int tp = tid >> 3;            // p = tp*2 + {0,1}

    unsigned long long a00 = 0ULL, a01 = 0ULL;   // p0: (j0,j1), (j2,j3)
    unsigned long long a10 = 0ULL, a11 = 0ULL;   // p1

    #pragma unroll 8
    for (int l = 0; l < LBLK; l++) {
        const float2 xv = *(const float2*)&Xs[l][tp * 2];
        const ulonglong2 bq = *(const ulonglong2*)&Bs[l][tn];  // w pre-applied
        unsigned long long xd0, xd1;
        asm("mov.b64 %0, {%1, %1};" : "=l"(xd0) : "r"(__float_as_uint(xv.x)));
        asm("mov.b64 %0, {%1, %1};" : "=l"(xd1) : "r"(__float_as_uint(xv.y)));
        asm("fma.rn.f32x2 %0, %1, %2, %0;" : "+l"(a00) : "l"(xd0), "l"(bq.x));
        asm("fma.rn.f32x2 %0, %1, %2, %0;" : "+l"(a01) : "l"(xd0), "l"(bq.y));
        asm("fma.rn.f32x2 %0, %1, %2, %0;" : "+l"(a10) : "l"(xd1), "l"(bq.x));
        asm("fma.rn.f32x2 %0, %1, %2, %0;" : "+l"(a11) : "l"(xd1), "l"(bq.y));
    }

    // packed pairs are little-endian (low float first) == float4 layout
    float* obase = out + ((size_t)(b * HEADS + h)) * DHEAD * DSTATE;
    *(ulonglong2*)(obase + (size_t)(tp * 2)     * DSTATE + n0 + tn * 4) =
        make_ulonglong2(a00, a01);
    *(ulonglong2*)(obase + (size_t)(tp * 2 + 1) * DSTATE + n0 + tn * 4) =
        make_ulonglong2(a10, a11);
}

extern "C" void kernel_launch(void* const* d_in, const int* in_sizes, int n_in,
                              void* d_out, int out_size)
{
    const float* X = (const float*)d_in[0];   // (2,4096,16,64)  f32
    const float* A = (const float*)d_in[1];   // (2,4096,16)     f32
    const float* B = (const float*)d_in[2];   // (2,4096,16,128) f32
    float* out = (float*)d_out;               // (2,16,64,128)   f32

    dim3 grid(BATCH * HEADS, DSTATE / 32);    // 32 x 4 = 128 CTAs
    chunk_state_last_kernel<<<grid, 256>>>(X, A, B, out);
}